// round 10
// baseline (speedup 1.0000x reference)
#include <cuda_runtime.h>
#include <cuda_bf16.h>
#include <cuda_fp16.h>
#include <cstring>

// KAN layer: y[b,o] = sum_f lerp(coeff[f, i-1, o], coeff[f, i, o], t) + bias[o]
// B=4096, F=128, G=64, OUT=64.  i = clip(ceil((x+3)*10.5), 1, 63); t = (x+3)*10.5-(i-1)
//
// R9: issue-count surgery. Convert kernel precomputes fp16 (c0, delta) planes at a
// fixed 1MB distance: lerp = one HFMA2, one address computation serves both LDG.32
// (imm-offset second load), each load touches exactly one 128B line.
// Per-pair instruction stream ~10 (was ~18). fp32 accumulate preserved.

#define F_DIM   128
#define G_SIZE  64
#define OUT_N   64
#define SPB     4                 // samples per block
#define THREADS 256               // 8 warps = 4 samples x 2 feature-halves
#define B_TOTAL 4096
#define FH      64                // features per warp

#define PLANE_HALVES (F_DIM * G_SIZE * OUT_N)     // 524288 halves = 1 MB
#define PLANE_BYTES  (PLANE_HALVES * 2)           // 0x100000

// plane 0: c0 = coeff[f][g][o]; plane 1: d = coeff[f][g+1][o] - coeff[f][g][o]
__device__ __half g_planes[2 * PLANE_HALVES];     // 2 MB

// Build c0 + delta planes. 131072 threads, one per (f, g, o4).
__global__ __launch_bounds__(256)
void kan_convert_kernel(const float* __restrict__ coeff)
{
    const int j   = blockIdx.x * 256 + threadIdx.x;   // 0..131071
    const int f   = j >> 10;
    const int rem = j & 1023;
    const int g   = rem >> 4;                 // 0..63
    const int o4  = (rem & 15) << 2;
    const int gn  = min(g + 1, G_SIZE - 1);

    const float4 r0 = *reinterpret_cast<const float4*>(coeff + ((f * G_SIZE + g ) * OUT_N) + o4);
    const float4 r1 = *reinterpret_cast<const float4*>(coeff + ((f * G_SIZE + gn) * OUT_N) + o4);

    __half2 c0a = __float22half2_rn(make_float2(r0.x, r0.y));
    __half2 c0b = __float22half2_rn(make_float2(r0.z, r0.w));
    __half2 da  = __float22half2_rn(make_float2(r1.x - r0.x, r1.y - r0.y));
    __half2 db  = __float22half2_rn(make_float2(r1.z - r0.z, r1.w - r0.w));

    const int idx = (f * G_SIZE + g) * OUT_N + o4;    // half-elem offset
    *reinterpret_cast<__half2*>(g_planes + idx)                    = c0a;
    *reinterpret_cast<__half2*>(g_planes + idx + 2)                = c0b;
    *reinterpret_cast<__half2*>(g_planes + PLANE_HALVES + idx)     = da;
    *reinterpret_cast<__half2*>(g_planes + PLANE_HALVES + idx + 2) = db;
}

__global__ __launch_bounds__(THREADS, 6)
void kan_main_kernel(const float* __restrict__ x,
                     const float* __restrict__ bias,
                     float* __restrict__ y)
{
    __shared__ uint2  sidx[SPB * F_DIM];    // 4 KB: (.x = byte offset of row, .y = half2(t,t))
    __shared__ float2 part[SPB][32];        // 1 KB

    const int tid  = threadIdx.x;
    const int row0 = blockIdx.x * SPB;

    // ---- Phase 1: (sample, feature) -> (byte offset, packed t), once ----
    #pragma unroll
    for (int k = 0; k < (SPB * F_DIM) / THREADS; ++k) {
        const int p = tid + k * THREADS;
        const int s = p >> 7;
        const int f = p & (F_DIM - 1);          // coalesced over f
        const float xv = x[(row0 + s) * F_DIM + f];
        const float u  = (xv + 3.0f) * 10.5f;
        int i = (int)ceilf(u);
        i = max(1, min(i, G_SIZE - 1));
        const float t = u - (float)(i - 1);
        const __half2 th = __float2half2_rn(t);
        unsigned tb; memcpy(&tb, &th, 4);
        const unsigned off = (unsigned)(((f * G_SIZE + (i - 1)) * OUT_N) * 2);  // bytes
        sidx[p] = make_uint2(off, tb);
    }
    __syncthreads();

    // ---- Phase 2: warp = (sample, feature-half); lane owns outputs {2l, 2l+1} ----
    const int w    = tid >> 5;
    const int lane = tid & 31;
    const int s    = w >> 1;
    const int h    = w & 1;

    const uint2* sp = sidx + s * F_DIM + h * FH;
    const char* cbase = reinterpret_cast<const char*>(g_planes) + lane * 4;

    float2 acc = make_float2(0.f, 0.f);

    for (int f0 = 0; f0 < FH; f0 += 4) {
        __half2 c0[4], dd[4], t2[4];
        #pragma unroll
        for (int j = 0; j < 4; ++j) {
            const uint2 e = sp[f0 + j];
            memcpy(&t2[j], &e.y, 4);
            const char* a = cbase + e.x;               // one address per feature
            c0[j] = *reinterpret_cast<const __half2*>(a);                // line A
            dd[j] = *reinterpret_cast<const __half2*>(a + PLANE_BYTES);  // imm offset
        }
        #pragma unroll
        for (int j = 0; j < 4; ++j) {
            const __half2 r = __hfma2(t2[j], dd[j], c0[j]);   // single-instr lerp
            const float2 rf = __half22float2(r);
            acc.x += rf.x;
            acc.y += rf.y;
        }
    }

    // ---- Phase 3: pair reduction + bias + store ----
    if (h == 1) part[s][lane] = acc;
    __syncthreads();
    if (h == 0) {
        const float2 pr = part[s][lane];
        const float2 bv = reinterpret_cast<const float2*>(bias)[lane];
        acc.x += pr.x + bv.x;
        acc.y += pr.y + bv.y;
        reinterpret_cast<float2*>(y + (row0 + s) * OUT_N)[lane] = acc;
    }
}

extern "C" void kernel_launch(void* const* d_in, const int* in_sizes, int n_in,
                              void* d_out, int out_size)
{
    const float* x     = (const float*)d_in[0];   // [4096, 128]
    const float* coeff = (const float*)d_in[1];   // [128, 64, 64]
    const float* bias  = (const float*)d_in[2];   // [64]
    float* y           = (float*)d_out;           // [4096, 64]

    kan_convert_kernel<<<F_DIM * G_SIZE * OUT_N / 4 / 256, 256>>>(coeff);
    kan_main_kernel<<<B_TOTAL / SPB, THREADS>>>(x, bias, y);
}

// round 11
// speedup vs baseline: 1.0530x; 1.0530x over previous
#include <cuda_runtime.h>
#include <cuda_bf16.h>
#include <cuda_fp16.h>
#include <cstring>

// KAN layer: y[b,o] = sum_f lerp(coeff[f, i-1, o], coeff[f, i, o], t) + bias[o]
// B=4096, F=128, G=64, OUT=64.  i = clip(ceil((x+3)*10.5), 1, 63); t = (x+3)*10.5-(i-1)
//
// R10: instruction-stream surgery around the LDG LSU floor (1.05M LDG x 1.82cyc/SM
// = 6.6us). Per (warp,feature) stream cut 18 -> ~9:
//  - ONE 32-bit IADD3 (off = e.x + lane*4); both plane LDGs reuse the same R
//    offset against two uniform bases (no 64-bit address pairs like R9).
//  - sidx packed 2 features per LDS.128 broadcast (uint4: off0,t0,off1,t1).
//  - HFMA2 lerp, fp32 accumulate (fp16 accum chains pencil out too close to the
//    1e-3 gate).

#define F_DIM   128
#define G_SIZE  64
#define OUT_N   64
#define SPB     4
#define THREADS 256               // 8 warps = 4 samples x 2 feature-halves
#define B_TOTAL 4096
#define FH      64                // features per warp

#define PLANE_HALVES (F_DIM * G_SIZE * OUT_N)     // 1 MB
#define PLANE_BYTES  (PLANE_HALVES * 2)

// plane 0: c0 fp16; plane 1: d = c1 - c0 fp16
__device__ __half g_planes[2 * PLANE_HALVES];

// Build c0 + delta planes. One thread per (f, g, 4 outputs).
__global__ __launch_bounds__(256)
void kan_convert_kernel(const float* __restrict__ coeff)
{
    const int j   = blockIdx.x * 256 + threadIdx.x;   // 0..131071
    const int f   = j >> 10;
    const int rem = j & 1023;
    const int g   = rem >> 4;
    const int o4  = (rem & 15) << 2;
    const int gn  = min(g + 1, G_SIZE - 1);

    const float4 r0 = __ldg(reinterpret_cast<const float4*>(coeff + ((f * G_SIZE + g ) * OUT_N) + o4));
    const float4 r1 = __ldg(reinterpret_cast<const float4*>(coeff + ((f * G_SIZE + gn) * OUT_N) + o4));

    const int idx = (f * G_SIZE + g) * OUT_N + o4;
    *reinterpret_cast<__half2*>(g_planes + idx)     = __float22half2_rn(make_float2(r0.x, r0.y));
    *reinterpret_cast<__half2*>(g_planes + idx + 2) = __float22half2_rn(make_float2(r0.z, r0.w));
    *reinterpret_cast<__half2*>(g_planes + PLANE_HALVES + idx)     = __float22half2_rn(make_float2(r1.x - r0.x, r1.y - r0.y));
    *reinterpret_cast<__half2*>(g_planes + PLANE_HALVES + idx + 2) = __float22half2_rn(make_float2(r1.z - r0.z, r1.w - r0.w));
}

__global__ __launch_bounds__(THREADS, 6)
void kan_main_kernel(const float* __restrict__ x,
                     const float* __restrict__ bias,
                     float* __restrict__ y)
{
    // sidx4[s*64 + fp] covers features {2fp, 2fp+1}: {off0_bytes, t0_h2, off1_bytes, t1_h2}
    __shared__ uint4  sidx4[SPB * F_DIM / 2];   // 4 KB
    __shared__ float2 part[SPB][32];            // 1 KB

    const int tid  = threadIdx.x;
    const int row0 = blockIdx.x * SPB;

    // ---- Phase 1: each thread computes 2 consecutive features of one sample ----
    {
        const int s  = tid >> 6;            // 0..3
        const int fp = tid & 63;            // feature pair
        const int f0 = fp << 1;
        const float2 xv = *reinterpret_cast<const float2*>(x + (row0 + s) * F_DIM + f0);

        uint4 e;
        {
            const float u = (xv.x + 3.0f) * 10.5f;
            int i = (int)ceilf(u);
            i = max(1, min(i, G_SIZE - 1));
            const __half2 th = __float2half2_rn(u - (float)(i - 1));
            memcpy(&e.y, &th, 4);
            e.x = (unsigned)(((f0 * G_SIZE + (i - 1)) * OUT_N) * 2);
        }
        {
            const float u = (xv.y + 3.0f) * 10.5f;
            int i = (int)ceilf(u);
            i = max(1, min(i, G_SIZE - 1));
            const __half2 th = __float2half2_rn(u - (float)(i - 1));
            memcpy(&e.w, &th, 4);
            e.z = (unsigned)((((f0 + 1) * G_SIZE + (i - 1)) * OUT_N) * 2);
        }
        sidx4[tid] = e;
    }
    __syncthreads();

    // ---- Phase 2: warp = (sample, feature-half); lane owns outputs {2l, 2l+1} ----
    const int w    = tid >> 5;
    const int lane = tid & 31;
    const int s    = w >> 1;
    const int h    = w & 1;

    const uint4* sp = sidx4 + s * (F_DIM / 2) + h * (FH / 2);
    const char* pc0 = reinterpret_cast<const char*>(g_planes);               // uniform base
    const char* pd  = reinterpret_cast<const char*>(g_planes) + PLANE_BYTES; // uniform base
    const unsigned lane4 = lane * 4;

    float2 acc = make_float2(0.f, 0.f);

    #pragma unroll 4
    for (int j2 = 0; j2 < FH / 4; ++j2) {      // 4 features per iteration
        const uint4 e0 = sp[2 * j2];           // LDS.128 broadcast
        const uint4 e1 = sp[2 * j2 + 1];

        const unsigned o0 = e0.x + lane4;      // one IADD3 per feature
        const unsigned o1 = e0.z + lane4;
        const unsigned o2 = e1.x + lane4;
        const unsigned o3 = e1.z + lane4;

        const __half2 c0a = *reinterpret_cast<const __half2*>(pc0 + o0);
        const __half2 dda = *reinterpret_cast<const __half2*>(pd  + o0);
        const __half2 c0b = *reinterpret_cast<const __half2*>(pc0 + o1);
        const __half2 ddb = *reinterpret_cast<const __half2*>(pd  + o1);
        const __half2 c0c = *reinterpret_cast<const __half2*>(pc0 + o2);
        const __half2 ddc = *reinterpret_cast<const __half2*>(pd  + o2);
        const __half2 c0d = *reinterpret_cast<const __half2*>(pc0 + o3);
        const __half2 ddd = *reinterpret_cast<const __half2*>(pd  + o3);

        __half2 t2a, t2b, t2c, t2d;
        memcpy(&t2a, &e0.y, 4);
        memcpy(&t2b, &e0.w, 4);
        memcpy(&t2c, &e1.y, 4);
        memcpy(&t2d, &e1.w, 4);

        const float2 ra = __half22float2(__hfma2(t2a, dda, c0a));
        const float2 rb = __half22float2(__hfma2(t2b, ddb, c0b));
        const float2 rc = __half22float2(__hfma2(t2c, ddc, c0c));
        const float2 rd = __half22float2(__hfma2(t2d, ddd, c0d));

        acc.x += ra.x + rb.x + rc.x + rd.x;
        acc.y += ra.y + rb.y + rc.y + rd.y;
    }

    // ---- Phase 3: pair reduction + bias + store ----
    if (h == 1) part[s][lane] = acc;
    __syncthreads();
    if (h == 0) {
        const float2 pr = part[s][lane];
        const float2 bv = reinterpret_cast<const float2*>(bias)[lane];
        acc.x += pr.x + bv.x;
        acc.y += pr.y + bv.y;
        reinterpret_cast<float2*>(y + (row0 + s) * OUT_N)[lane] = acc;
    }
}

extern "C" void kernel_launch(void* const* d_in, const int* in_sizes, int n_in,
                              void* d_out, int out_size)
{
    const float* x     = (const float*)d_in[0];   // [4096, 128]
    const float* coeff = (const float*)d_in[1];   // [128, 64, 64]
    const float* bias  = (const float*)d_in[2];   // [64]
    float* y           = (float*)d_out;           // [4096, 64]

    kan_convert_kernel<<<F_DIM * G_SIZE * OUT_N / 4 / 256, 256>>>(coeff);
    kan_main_kernel<<<B_TOTAL / SPB, THREADS>>>(x, bias, y);
}

// round 12
// speedup vs baseline: 1.1163x; 1.0601x over previous
#include <cuda_runtime.h>
#include <cuda_bf16.h>
#include <cuda_fp16.h>
#include <cstring>

// KAN layer: y[b,o] = sum_f lerp(coeff[f, i-1, o], coeff[f, i, o], t) + bias[o]
// B=4096, F=128, G=64, OUT=64.  i = clip(ceil((x+3)*10.5), 1, 63); t = (x+3)*10.5-(i-1)
//
// R11: interleaved (c0, delta) fp16 tensor -> ONE LDG.64 per (warp, feature).
// Row (f,g) = 256 B; lane l's 8 bytes = {c0[2l], c0[2l+1], d[2l], d[2l+1]}.
// R10 post-mortem showed ~21 instrs/pair, mostly 64-bit address IADD pairs for
// 2 loads x 2 planes; this cuts it to 1 address + 1 load. Pairwise HADD2 before
// cvt halves the conversion/accumulate cost (error pencil: +~1e-4, total ~4.5e-4).

#define F_DIM   128
#define G_SIZE  64
#define OUT_N   64
#define SPB     4
#define THREADS 256               // 8 warps = 4 samples x 2 feature-halves
#define B_TOTAL 4096
#define FH      64                // features per warp
#define ROW_BYTES 256             // 64 outputs x {c0,c0,d,d} halves / 32 lanes * 8B

// interleaved fp16 tensor: [F][G][32 lanes][4 halves] = 2 MB
__device__ __align__(16) __half g_ilv[F_DIM * G_SIZE * OUT_N * 2];

// One thread per (f, g, output-pair). Coalesced float2 reads, 8 B writes.
__global__ __launch_bounds__(256)
void kan_convert_kernel(const float* __restrict__ coeff)
{
    const int j  = blockIdx.x * 256 + threadIdx.x;   // 0..262143
    const int f  = j >> 11;
    const int g  = (j >> 5) & (G_SIZE - 1);
    const int op = j & 31;                           // output pair -> lane
    const int gn = min(g + 1, G_SIZE - 1);

    const float2 c0 = __ldg(reinterpret_cast<const float2*>(
        coeff + (f * G_SIZE + g ) * OUT_N) + op);
    const float2 c1 = __ldg(reinterpret_cast<const float2*>(
        coeff + (f * G_SIZE + gn) * OUT_N) + op);

    __half2 h0 = __float22half2_rn(c0);
    __half2 hd = __float22half2_rn(make_float2(c1.x - c0.x, c1.y - c0.y));

    uint2 v;
    memcpy(&v.x, &h0, 4);
    memcpy(&v.y, &hd, 4);
    reinterpret_cast<uint2*>(g_ilv)[j] = v;          // row-major: (f*G+g)*32 + op
}

__global__ __launch_bounds__(THREADS, 6)
void kan_main_kernel(const float* __restrict__ x,
                     const float* __restrict__ bias,
                     float* __restrict__ y)
{
    // sidx4[s*64 + fp] covers features {2fp, 2fp+1}: {off0_bytes, t0_h2, off1_bytes, t1_h2}
    __shared__ uint4  sidx4[SPB * F_DIM / 2];   // 4 KB
    __shared__ float2 part[SPB][32];            // 1 KB

    const int tid  = threadIdx.x;
    const int row0 = blockIdx.x * SPB;

    // ---- Phase 1: each thread -> 2 consecutive features of one sample ----
    {
        const int s  = tid >> 6;
        const int fp = tid & 63;
        const int f0 = fp << 1;
        const float2 xv = *reinterpret_cast<const float2*>(x + (row0 + s) * F_DIM + f0);

        uint4 e;
        {
            const float u = (xv.x + 3.0f) * 10.5f;
            int i = (int)ceilf(u);
            i = max(1, min(i, G_SIZE - 1));
            const __half2 th = __float2half2_rn(u - (float)(i - 1));
            memcpy(&e.y, &th, 4);
            e.x = (unsigned)((f0 * G_SIZE + (i - 1)) * ROW_BYTES);
        }
        {
            const float u = (xv.y + 3.0f) * 10.5f;
            int i = (int)ceilf(u);
            i = max(1, min(i, G_SIZE - 1));
            const __half2 th = __float2half2_rn(u - (float)(i - 1));
            memcpy(&e.w, &th, 4);
            e.z = (unsigned)(((f0 + 1) * G_SIZE + (i - 1)) * ROW_BYTES);
        }
        sidx4[tid] = e;
    }
    __syncthreads();

    // ---- Phase 2: warp = (sample, feature-half); lane owns outputs {2l, 2l+1} ----
    const int w    = tid >> 5;
    const int lane = tid & 31;
    const int s    = w >> 1;
    const int h    = w & 1;

    const uint4* sp = sidx4 + s * (F_DIM / 2) + h * (FH / 2);
    const char* base = reinterpret_cast<const char*>(g_ilv);
    const unsigned lane8 = lane * 8;

    float2 acc = make_float2(0.f, 0.f);

    #pragma unroll 4
    for (int jp = 0; jp < FH / 2; ++jp) {          // 2 features per iteration
        const uint4 e = sp[jp];                    // LDS.128 broadcast

        const uint2 v0 = *reinterpret_cast<const uint2*>(base + (e.x + lane8));
        const uint2 v1 = *reinterpret_cast<const uint2*>(base + (e.z + lane8));

        __half2 c00, d0, c01, d1, t0, t1;
        memcpy(&c00, &v0.x, 4);
        memcpy(&d0,  &v0.y, 4);
        memcpy(&c01, &v1.x, 4);
        memcpy(&d1,  &v1.y, 4);
        memcpy(&t0,  &e.y,  4);
        memcpy(&t1,  &e.w,  4);

        const __half2 r0 = __hfma2(t0, d0, c00);
        const __half2 r1 = __hfma2(t1, d1, c01);
        const __half2 rs = __hadd2(r0, r1);        // pairwise fp16 combine
        const float2  rf = __half22float2(rs);
        acc.x += rf.x;                              // fp32 accumulate
        acc.y += rf.y;
    }

    // ---- Phase 3: pair reduction + bias + store ----
    if (h == 1) part[s][lane] = acc;
    __syncthreads();
    if (h == 0) {
        const float2 pr = part[s][lane];
        const float2 bv = reinterpret_cast<const float2*>(bias)[lane];
        acc.x += pr.x + bv.x;
        acc.y += pr.y + bv.y;
        reinterpret_cast<float2*>(y + (row0 + s) * OUT_N)[lane] = acc;
    }
}

extern "C" void kernel_launch(void* const* d_in, const int* in_sizes, int n_in,
                              void* d_out, int out_size)
{
    const float* x     = (const float*)d_in[0];   // [4096, 128]
    const float* coeff = (const float*)d_in[1];   // [128, 64, 64]
    const float* bias  = (const float*)d_in[2];   // [64]
    float* y           = (float*)d_out;           // [4096, 64]

    kan_convert_kernel<<<F_DIM * G_SIZE * OUT_N / 2 / 256, 256>>>(coeff);
    kan_main_kernel<<<B_TOTAL / SPB, THREADS>>>(x, bias, y);
}